// round 17
// baseline (speedup 1.0000x reference)
#include <cuda_runtime.h>

// DifferentiableBezierRenderer — row-binned two-kernel version (v4).
//
// wind[y][gx] = sum_e c_e(y) * sigmoid(xc_e(y) - gx)
//   c, xc depend only on (edge,row); sigmoid saturates outside |z| > TB.
//
// kA (bin): one warp per edge. Computes the edge's active row span
//   (t in [-1.2, 2.2]) and appends (c, xc) records into per-row global
//   buckets. ~60K records total vs the 1M pair tests v3 did per frame.
// kB (render): block y consumes ONLY its ~120 records:
//   - step part (gx < xc-TB contributes exactly c): difference array + scan
//   - band part (<=32 cols, TB=15.5): records bucketed into the 16
//     warp-owned 32-col windows; warp gathers its bucket into registers.
// kB zeroes g_cnt[y] at the end -> invariant: g_cnt==0 at every launch
// (module load zero-init covers the first call; graph replays in order).

#define HH 512
#define WW 512
#define MM 2048           // 64 segments * 32 samples
#define TB 15.5f          // band half-width; tail err ~e^-15.5 ~ 1.8e-7
#define CAP 2048          // records per row (actual ~120)
#define FCAP 4096         // band-record smem capacity (<= 2*CAP worst case)

__device__ float2 g_rec[HH * CAP];   // (c, xc) per active (edge,row)
__device__ int    g_cnt[HH];         // zero-initialized at module load

// ---------------------------------------------------------------------------
// kA: bezier sampling + per-edge row binning. grid = 128 blocks x 512.
// One warp per edge (128*16 = 2048 warps).
// ---------------------------------------------------------------------------
__global__ void __launch_bounds__(512)
k_bin(const float* __restrict__ cp)
{
    __shared__ float scp[386];
    __shared__ float spx[MM];
    __shared__ float spy[MM];

    const int tid  = threadIdx.x;
    const int lane = tid & 31;
    const int wid  = tid >> 5;

    if (tid < 386) scp[tid] = cp[tid];
    __syncthreads();

    // all 2048 points per block (warp shares a segment: LDS broadcasts)
    #pragma unroll
    for (int k = 0; k < 4; ++k) {
        int idx = tid + k * 512;
        int s = idx >> 5;            // segment 0..63
        int i = idx & 31;            // sample 0..31
        float t  = (float)i * (1.0f / 31.0f);   // linspace(0,1,32)
        float mt = 1.0f - t;
        float w0 = mt * mt * mt;
        float w1 = 3.0f * mt * mt * t;
        float w2 = 3.0f * mt * t * t;
        float w3 = t * t * t;
        const float* c0 = scp + 6 * s;
        spx[idx] = w0 * c0[0] + w1 * c0[2] + w2 * c0[4] + w3 * c0[6];
        spy[idx] = w0 * c0[1] + w1 * c0[3] + w2 * c0[5] + w3 * c0[7];
    }
    __syncthreads();

    const int e  = blockIdx.x * 16 + wid;      // this warp's edge
    const int e1 = (e + 1) & (MM - 1);

    float y0 = spy[e];
    float dy = spy[e1] - y0;
    if (fabsf(dy) < 1e-6f) return;             // reference mask (warp-uniform)

    float dys = dy + 1e-8f;                    // reference's exact offset
    float rdy = __fdividef(1.0f, dys);         // sign(rdy) == sign(dy)
    float x0  = spx[e];
    float dxe = spx[e1] - x0;

    // rows where t = (y - y0)*rdy falls in [-1.2, 2.2] (c >= ~4e-11)
    float ya = fmaf(-1.2f, dys, y0);
    float yb = fmaf( 2.2f, dys, y0);
    int ylo = (int)ceilf (fminf(ya, yb)); if (ylo < 0)   ylo = 0;
    int yhi = (int)floorf(fmaxf(ya, yb)); if (yhi > 511) yhi = 511;

    for (int yy = ylo + lane; yy <= yhi; yy += 32) {
        float t  = ((float)yy - y0) * rdy;
        // valid_t = sigm(20t)*sigm(20(1-t)) = 1/((1+e^-20t)(1+e^(20t-20)))
        float em = __expf(-20.0f * t);
        float ep = __expf(20.0f * t - 20.0f);
        float c  = __fdividef(1.0f, (1.0f + em) * (1.0f + ep));
        if (c < 1e-9f) continue;
        if (rdy < 0.0f) c = -c;                // * sign(dy)
        float xc = fmaf(t, dxe, x0);
        if (ceilf(xc - TB) + 31.0f < 0.0f) continue;   // fully off-left
        int pos = atomicAdd(&g_cnt[yy], 1);
        if (pos < CAP) g_rec[yy * CAP + pos] = make_float2(c, xc);
    }
}

// ---------------------------------------------------------------------------
// kB: per-row resolve. grid = 512 blocks x 512 threads (block y = row y).
// ---------------------------------------------------------------------------
__global__ void __launch_bounds__(512, 4)
k_render(const float* __restrict__ color,
         float* __restrict__ out)
{
    __shared__ float  sD[WW];        // step difference array
    __shared__ float2 flat[FCAP];    // bucketed band records
    __shared__ int    bcount[16], boff[16], bfill[16];
    __shared__ float  wsum[16];

    const int tid  = threadIdx.x;
    const int y    = blockIdx.x;
    const int lane = tid & 31;
    const int wid  = tid >> 5;

    sD[tid] = 0.0f;
    if (tid < 16) { bcount[tid] = 0; bfill[tid] = 0; }
    __syncthreads();

    int n = g_cnt[y]; if (n > CAP) n = CAP;

    // ---- pass 1: step scatter + bucket counts ----
    float cstep = 0.0f;
    for (int i = tid; i < n; i += 512) {
        float2 r = g_rec[y * CAP + i];
        float gl = ceilf(r.y - TB);
        if (gl > 0.0f) {                       // +c on columns [0, min(gl,512))
            cstep += r.x;
            if (gl < 512.0f) atomicAdd(&sD[(int)gl], -r.x);
        }
        if (gl < 512.0f) {                     // band reaches screen
            int igl = (int)gl;
            int b0 = (igl < 0 ? 0 : igl) >> 5;
            int hi = igl + 31; if (hi > 511) hi = 511;
            atomicAdd(&bcount[b0], 1);
            if ((hi >> 5) != b0) atomicAdd(&bcount[hi >> 5], 1);
        }
    }
    #pragma unroll
    for (int o = 16; o > 0; o >>= 1)
        cstep += __shfl_xor_sync(0xffffffffu, cstep, o);
    if (lane == 0 && cstep != 0.0f) atomicAdd(&sD[0], cstep);
    __syncthreads();

    // ---- exclusive prefix over 16 bucket counts ----
    if (wid == 0) {
        int v = (lane < 16) ? bcount[lane] : 0;
        int s = v;
        #pragma unroll
        for (int o = 1; o < 16; o <<= 1) {
            int m = __shfl_up_sync(0xffffffffu, s, o);
            if (lane >= o) s += m;
        }
        if (lane < 16) boff[lane] = s - v;
    }
    __syncthreads();

    // ---- pass 2: fill band buckets (records re-read: L1 hit) ----
    for (int i = tid; i < n; i += 512) {
        float2 r = g_rec[y * CAP + i];
        float gl = ceilf(r.y - TB);
        if (gl >= 512.0f) continue;
        int igl = (int)gl;
        int b0 = (igl < 0 ? 0 : igl) >> 5;
        int hi = igl + 31; if (hi > 511) hi = 511;
        int b1 = hi >> 5;
        int p = atomicAdd(&bfill[b0], 1);
        int q = boff[b0] + p; if (q < FCAP) flat[q] = r;
        if (b1 != b0) {
            p = atomicAdd(&bfill[b1], 1);
            q = boff[b1] + p; if (q < FCAP) flat[q] = r;
        }
    }
    __syncthreads();

    // ---- band gather: warp w owns columns [32w, 32w+31]; registers only ----
    float acc = 0.0f;
    const float fgx = (float)tid;
    {
        int base = boff[wid];
        int lim  = base + bcount[wid];
        if (lim > FCAP) lim = FCAP;
        for (int i = base; i < lim; ++i) {
            float2 pr = flat[i];               // LDS.64 broadcast
            float rel = fgx - ceilf(pr.y - TB);
            if (rel >= 0.0f && rel < 32.0f)    // sigm(xc - gx)
                acc += pr.x * __fdividef(1.0f, 1.0f + __expf(fgx - pr.y));
        }
    }

    // ---- inclusive scan of sD, combine, sigmoid, RGBA store ----
    float v = sD[tid];
    #pragma unroll
    for (int o = 1; o < 32; o <<= 1) {
        float m = __shfl_up_sync(0xffffffffu, v, o);
        if (lane >= o) v += m;
    }
    if (lane == 31) wsum[wid] = v;
    __syncthreads();
    if (wid == 0) {
        float w = (lane < 16) ? wsum[lane] : 0.0f;
        #pragma unroll
        for (int o = 1; o < 16; o <<= 1) {
            float m = __shfl_up_sync(0xffffffffu, w, o);
            if (lane >= o) w += m;
        }
        if (lane < 16) wsum[lane] = w;
    }
    __syncthreads();

    float prefix = (wid > 0) ? wsum[wid - 1] : 0.0f;
    float wind   = v + prefix + acc;
    float alpha  = __fdividef(1.0f, 1.0f + __expf(-4.0f * wind));

    float4 px = make_float4(color[0], color[1], color[2], alpha);
    reinterpret_cast<float4*>(out)[y * WW + tid] = px;

    if (tid == 0) g_cnt[y] = 0;    // reset for next graph replay
}

// ---------------------------------------------------------------------------
extern "C" void kernel_launch(void* const* d_in, const int* in_sizes, int n_in,
                              void* d_out, int out_size) {
    const float* cp    = (const float*)d_in[0];   // (193,2) f32
    const float* color = (const float*)d_in[1];   // (3,)   f32
    float* out = (float*)d_out;                   // (512,512,4) f32

    k_bin<<<128, 512>>>(cp);
    k_render<<<HH, 512>>>(color, out);
}